// round 10
// baseline (speedup 1.0000x reference)
#include <cuda_runtime.h>
#include <cuda_bf16.h>
#include <stdint.h>

#define BS 8
#define CH 256
#define HH 128
#define WW 128
#define HW (HH*WW)          /* 16384 */
#define NA 9
#define KTOP 100
#define NDET (BS*KTOP)      /* 800 */
#define FDIM (CH*NA)        /* 2304 */
#define KSPL (3*FDIM)       /* 6912 */
#define MPAD 896
#define HID 1024
#define NBINS 4096
#define CAND 512
#define SAFE_BIN 4088
#define BHW (NA*HW)         /* 147456 */
#define HMTOT (BS*BHW)      /* 1179648 */
#define HBLK 18             /* hist blocks per batch */

/* front-kernel block layout (bid-ordered: producers before consumers) */
#define NB_HIST (HBLK*BS)              /* 144 */
#define SEL_BASE NB_HIST               /* 144 */
#define ROI_BASE (SEL_BASE + BS)       /* 152 */
#define PREP_BASE (ROI_BASE + NDET)    /* 952 */
#define NB_PREP ((FDIM/64)*(HID/32))   /* 1152 */
#define NB_FRONT (PREP_BASE + NB_PREP) /* 2104 */

#define OFF_HM    0
#define OFF_WH1   1179648
#define OFF_OFF1  1182848
#define OFF_CLS1  1184448
#define OFF_WH2   1185248
#define OFF_OFF2  1188448
#define OFF_S2CLS 1190048
#define OFF_S2WH  1198048
#define OFF_INDS  1201248
#define OFF_VAL   1202048

// ---------------- scratch ----------------
__device__ int                g_hist[BS*NBINS];   // .bss zero; self-cleaned in select role
__device__ int                g_ccnt[BS];
__device__ unsigned long long g_cand[BS*CAND];
__device__ float              g_boxes[NDET*4];
__device__ int                g_histdone;         // reset in k_gemm_mma
__device__ int                g_boxready[BS];     // reset in k_gemm_mma
__device__ __align__(16) __nv_bfloat16 g_abf[MPAD*KSPL];   // rows >= NDET stay zero forever
__device__ __align__(16) __nv_bfloat16 g_bbf[HID*KSPL];

__device__ __forceinline__ uint32_t smem_u32(const void* p) {
    uint32_t a;
    asm("{ .reg .u64 t; cvta.to.shared.u64 t, %1; cvt.u32.u64 %0, t; }" : "=r"(a) : "l"(p));
    return a;
}
__device__ __forceinline__ void cp_async16(uint32_t d, const void* s) {
    unsigned long long g;
    asm("cvta.to.global.u64 %0, %1;" : "=l"(g) : "l"(s));
    asm volatile("cp.async.cg.shared.global [%0], [%1], 16;" :: "r"(d), "l"(g));
}
__device__ __forceinline__ void ldmatrix_x4(uint32_t* r, uint32_t addr) {
    asm volatile("ldmatrix.sync.aligned.m8n8.x4.shared.b16 {%0,%1,%2,%3}, [%4];"
        : "=r"(r[0]), "=r"(r[1]), "=r"(r[2]), "=r"(r[3]) : "r"(addr));
}
__device__ __forceinline__ void mma16816(float* d, const uint32_t* a, const uint32_t* b) {
    asm volatile("mma.sync.aligned.m16n8k16.row.col.f32.bf16.bf16.f32 "
        "{%0,%1,%2,%3}, {%4,%5,%6,%7}, {%8,%9}, {%0,%1,%2,%3};"
        : "+f"(d[0]), "+f"(d[1]), "+f"(d[2]), "+f"(d[3])
        : "r"(a[0]), "r"(a[1]), "r"(a[2]), "r"(a[3]), "r"(b[0]), "r"(b[1]));
}
__device__ __forceinline__ int val_bin(float v) {
    int bin = (int)(v * (float)NBINS);
    return bin < 0 ? 0 : (bin > NBINS-1 ? NBINS-1 : bin);
}
__device__ __forceinline__ unsigned long long make_key(float v, int il) {
    int a = il / HW, pix = il - a*HW;
    unsigned iflat = (unsigned)(pix * NA + a);
    return ((unsigned long long)__float_as_uint(v) << 32) | (0xFFFFFFFFu - iflat);
}

// ================ fused front kernel ================
__global__ void __launch_bounds__(256) k_front(const float* __restrict__ hm,
                       const float* __restrict__ feat,
                       const float* __restrict__ wh,  const float* __restrict__ offs,
                       const float* __restrict__ wfc1,
                       const float* __restrict__ bcls, const float* __restrict__ bwh,
                       float* __restrict__ out) {
    __shared__ union {
        int hist[NBINS];
        struct { unsigned long long sk[CAND]; int thr; int ovf; } sel;
        float prep[64][33];
    } u;
    int bid = blockIdx.x, tid = threadIdx.x;

    // ---------- role 1: hist + copy + candidate collect ----------
    if (bid < NB_HIST) {
        int b = bid / HBLK, xblk = bid % HBLK;
        #pragma unroll
        for (int q = 0; q < NBINS/256; ++q) u.hist[tid + q*256] = 0;
        __syncthreads();
        const int chunk = BHW/4/HBLK;                 // 2048 float4
        int base4 = b*(BHW/4) + xblk*chunk;
        const float4* src = (const float4*)hm + base4;
        float4* dst = (float4*)(out + OFF_HM) + base4;
        int il_base = xblk*chunk*4;
        #pragma unroll
        for (int q = 0; q < chunk/256; ++q) {
            int i = tid + q*256;
            float4 v4 = src[i];
            dst[i] = v4;
            float vv[4] = {v4.x, v4.y, v4.z, v4.w};
            #pragma unroll
            for (int e = 0; e < 4; ++e) {
                int bin = val_bin(vv[e]);
                atomicAdd(&u.hist[bin], 1);
                if (bin >= SAFE_BIN) {
                    unsigned long long key = make_key(vv[e], il_base + i*4 + e);
                    int p = atomicAdd(&g_ccnt[b], 1);
                    if (p < CAND) g_cand[b*CAND + p] = key;
                }
            }
        }
        __syncthreads();
        #pragma unroll
        for (int q = 0; q < NBINS/256; ++q) {
            int i = tid + q*256;
            int c = u.hist[i];
            if (c) atomicAdd(&g_hist[b*NBINS + i], c);
        }
        __threadfence();
        __syncthreads();
        if (tid == 0) atomicAdd(&g_histdone, 1);
        return;
    }

    // ---------- role 2: select (top-100 + detect + bias init) ----------
    if (bid < ROI_BASE) {
        int b = bid - SEL_BASE, lane = tid & 31, wid = tid >> 5;
        if (tid == 0) {                       // wait for all hist blocks
            while (atomicAdd(&g_histdone, 0) < NB_HIST) { }
        }
        __syncthreads();
        __threadfence();

        int rawcnt = g_ccnt[b];
        int C = rawcnt < CAND ? rawcnt : CAND;
        #pragma unroll
        for (int q = 0; q < CAND/256; ++q) {
            int i = tid + q*256;
            u.sel.sk[i] = (i < C) ? g_cand[b*CAND + i] : 0ULL;
        }
        if (wid == 0) {                       // exact threshold
            int cum = 0, found = 0, t = 0;
            for (int base = NBINS-32; base >= 0 && !found; base -= 32) {
                int c = g_hist[b*NBINS + base + lane];
                #pragma unroll
                for (int o = 1; o < 32; o <<= 1) {
                    int uu = __shfl_down_sync(0xffffffffu, c, o);
                    if (lane < 32 - o) c += uu;
                }
                unsigned m = __ballot_sync(0xffffffffu, cum + c >= KTOP);
                if (m) { t = base + (31 - __clz(m)); found = 1; }
                else cum += __shfl_sync(0xffffffffu, c, 0);
            }
            if (lane == 0) { u.sel.thr = t; u.sel.ovf = 0; }
        }
        __syncthreads();
        int thr = u.sel.thr;

        if (rawcnt > CAND || thr < SAFE_BIN) {        // exactness fallback
            const float* hb = hm + (size_t)b * BHW;
            for (int i = tid; i < BHW; i += 256) {
                float v = hb[i];
                if (val_bin(v) >= thr) {
                    int p = atomicAdd(&u.sel.ovf, 1);
                    if (p < CAND) u.sel.sk[p] = make_key(v, i);
                }
            }
            __syncthreads();
            int C2 = u.sel.ovf < CAND ? u.sel.ovf : CAND;
            #pragma unroll
            for (int q = 0; q < CAND/256; ++q) {
                int i = tid + q*256;
                if (i >= C2) u.sel.sk[i] = 0ULL;
            }
        }
        // self-clean for next replay
        for (int i = tid; i < NBINS; i += 256) g_hist[b*NBINS + i] = 0;
        if (tid == 0) g_ccnt[b] = 0;

        for (int k = 2; k <= CAND; k <<= 1)           // bitonic desc
            for (int j = k >> 1; j > 0; j >>= 1) {
                __syncthreads();
                int idx = ((tid & ~(j - 1)) << 1) | (tid & (j - 1));
                int ixj = idx | j;
                unsigned long long x = u.sel.sk[idx], y = u.sel.sk[ixj];
                bool desc = ((idx & k) == 0);
                if (desc ? (x < y) : (x > y)) { u.sel.sk[idx] = y; u.sel.sk[ixj] = x; }
            }
        __syncthreads();

        if (tid < KTOP) {
            int j = b*KTOP + tid;
            unsigned long long m = u.sel.sk[tid];
            float v = __uint_as_float((unsigned)(m >> 32));
            int iflat = (int)(0xFFFFFFFFu - (unsigned)(m & 0xFFFFFFFFu));
            int cls1 = iflat % NA;
            int pos  = iflat / NA;
            int inds = pos + b * HW;
            int a2 = inds % NA;        // select_tensor batch-0 quirk
            int p2 = inds / NA;
            float w0 = wh[(a2*4+0)*HW + p2];
            float w1 = wh[(a2*4+1)*HW + p2];
            float w2 = wh[(a2*4+2)*HW + p2];
            float w3 = wh[(a2*4+3)*HW + p2];
            float o0 = offs[(a2*2+0)*HW + p2];
            float o1 = offs[(a2*2+1)*HW + p2];
            float xs = (float)(inds % WW) + o0;
            float ys = (float)(inds / WW) + o1;
            g_boxes[j*4+0] = xs + w0; g_boxes[j*4+1] = ys + w1;
            g_boxes[j*4+2] = xs + w2; g_boxes[j*4+3] = ys + w3;
            out[OFF_WH1 + j*4+0] = w0; out[OFF_WH1 + j*4+1] = w1;
            out[OFF_WH1 + j*4+2] = w2; out[OFF_WH1 + j*4+3] = w3;
            out[OFF_WH2 + j*4+0] = w0; out[OFF_WH2 + j*4+1] = w1;
            out[OFF_WH2 + j*4+2] = w2; out[OFF_WH2 + j*4+3] = w3;
            out[OFF_OFF1 + j*2+0] = o0; out[OFF_OFF1 + j*2+1] = o1;
            out[OFF_OFF2 + j*2+0] = o0; out[OFF_OFF2 + j*2+1] = o1;
            out[OFF_CLS1 + j] = (float)cls1;
            out[OFF_INDS + j] = (float)inds;
            out[OFF_VAL  + j] = v;
            #pragma unroll
            for (int q = 0; q < 10; ++q) out[OFF_S2CLS + j*10 + q] = bcls[q];
            #pragma unroll
            for (int q = 0; q < 4;  ++q) out[OFF_S2WH  + j*4  + q] = bwh[q];
        }
        __threadfence();
        __syncthreads();
        if (tid == 0) atomicExch(&g_boxready[b], 1);
        return;
    }

    // ---------- role 3: ROI align -> bf16 split A' ----------
    if (bid < PREP_BASE) {
        int j = bid - ROI_BASE;
        int c = tid;
        int b = j / KTOP;
        if (tid == 0) {
            while (atomicAdd(&g_boxready[b], 0) == 0) { }
        }
        __syncthreads();
        __threadfence();
        float x1b = g_boxes[j*4+0], y1b = g_boxes[j*4+1];
        float x2b = g_boxes[j*4+2], y2b = g_boxes[j*4+3];
        float rw = fmaxf(x2b - x1b, 1.0f);
        float rh = fmaxf(y2b - y1b, 1.0f);
        float bw = rw / 3.0f;
        float bh = rh / 3.0f;
        const float* fb = feat + ((size_t)b*CH + c) * HW;
        #pragma unroll
        for (int pt = 0; pt < 9; ++pt) {
            int gy = pt / 3, gx = pt % 3;
            float sy = __fadd_rn(y1b, __fmul_rn((float)gy + 0.5f, bh));
            float sx = __fadd_rn(x1b, __fmul_rn((float)gx + 0.5f, bw));
            bool inv = (sy < -1.0f) || (sy > (float)HH) || (sx < -1.0f) || (sx > (float)WW);
            float r = 0.0f;
            if (!inv) {
                float y = fminf(fmaxf(sy, 0.0f), (float)(HH-1));
                float x = fminf(fmaxf(sx, 0.0f), (float)(WW-1));
                int y0 = (int)floorf(y), x0 = (int)floorf(x);
                int y1i = min(y0 + 1, HH-1), x1i = min(x0 + 1, WW-1);
                float ly = __fadd_rn(y, -(float)y0);
                float lx = __fadd_rn(x, -(float)x0);
                float hy = __fadd_rn(1.0f, -ly);
                float hx = __fadd_rn(1.0f, -lx);
                float v00, v01, v10, v11;
                if ((x0 & 1) == 0 && x0 < HH-1) {      // block-uniform branch
                    float2 t0 = *(const float2*)(fb + y0 *WW + x0);
                    float2 t1 = *(const float2*)(fb + y1i*WW + x0);
                    v00 = t0.x; v01 = t0.y; v10 = t1.x; v11 = t1.y;
                } else {
                    v00 = fb[y0 *WW + x0 ]; v01 = fb[y0 *WW + x1i];
                    v10 = fb[y1i*WW + x0 ]; v11 = fb[y1i*WW + x1i];
                }
                r = __fadd_rn(__fadd_rn(__fadd_rn(
                        __fmul_rn(__fmul_rn(hy,hx), v00),
                        __fmul_rn(__fmul_rn(hy,lx), v01)),
                        __fmul_rn(__fmul_rn(ly,hx), v10)),
                        __fmul_rn(__fmul_rn(ly,lx), v11));
            }
            __nv_bfloat16 hi = __float2bfloat16(r);
            __nv_bfloat16 lo = __float2bfloat16(__fadd_rn(r, -__bfloat162float(hi)));
            size_t base = (size_t)j*KSPL + 3*(pt*CH + c);
            g_abf[base+0] = hi;
            g_abf[base+1] = hi;
            g_abf[base+2] = lo;
        }
        return;
    }

    // ---------- role 4: B' prep ----------
    {
        int pid = bid - PREP_BASE;
        int t0 = (pid % (FDIM/64)) * 64, n0 = (pid / (FDIM/64)) * 32;
        int wp = tid >> 5, ln = tid & 31;
        #pragma unroll
        for (int q = 0; q < 8; ++q) {
            int tl = wp*8 + q;
            int t = t0 + tl;
            int pt = t >> 8, c = t & 255;
            u.prep[tl][ln] = wfc1[(size_t)(c*NA + pt)*HID + n0 + ln];
        }
        __syncthreads();
        int n = tid >> 3, tg = tid & 7;
        __nv_bfloat16 obuf[24];
        #pragma unroll
        for (int q = 0; q < 8; ++q) {
            float v = u.prep[tg*8 + q][n];
            __nv_bfloat16 hi = __float2bfloat16(v);
            __nv_bfloat16 lo = __float2bfloat16(v - __bfloat162float(hi));
            obuf[q*3+0] = hi; obuf[q*3+1] = lo; obuf[q*3+2] = hi;
        }
        uint4* dst = (uint4*)((char*)g_bbf + (size_t)(n0 + n)*(KSPL*2) + 6*(size_t)(t0 + tg*8));
        const uint4* sv = (const uint4*)obuf;
        dst[0] = sv[0]; dst[1] = sv[1]; dst[2] = sv[2];
    }
}

// ---------------- fc1 GEMM + fused stage2 heads ----------------
#define BM 128
#define BN 64
#define STAGE_BYTES 24576
#define KT_TOTAL (KSPL/64)    /* 108 */
__global__ void __launch_bounds__(256) k_gemm_mma(const float* __restrict__ bias,
                                                  const float* __restrict__ wcls,
                                                  const float* __restrict__ wwh,
                                                  float* __restrict__ out) {
    __shared__ __align__(1024) char smem[2*STAGE_BYTES];
    int tid = threadIdx.x, lane = tid & 31, w = tid >> 5;
    int bm = blockIdx.x * BM, bn = blockIdx.y * BN;
    int wm = w >> 1, wn = w & 1;

    // reset front-kernel flags for next graph replay (front kernel already complete)
    if (blockIdx.x == 0 && blockIdx.y == 0 && tid == 0) {
        g_histdone = 0;
        #pragma unroll
        for (int b = 0; b < BS; ++b) g_boxready[b] = 0;
    }

    const char* aG = (const char*)g_abf + (size_t)bm * (KSPL*2);
    const char* bG = (const char*)g_bbf + (size_t)bn * (KSPL*2);

    float acc[2][4][4];
    #pragma unroll
    for (int mi = 0; mi < 2; ++mi)
        #pragma unroll
        for (int ni = 0; ni < 4; ++ni)
            #pragma unroll
            for (int e = 0; e < 4; ++e) acc[mi][ni][e] = 0.0f;

    #define ISSUE_STAGE(kt, st) do {                                           \
        char* As_ = smem + (st)*STAGE_BYTES;                                   \
        char* Bs_ = As_ + 16384;                                               \
        _Pragma("unroll")                                                      \
        for (int q = 0; q < 4; ++q) {                                          \
            int id = tid + q*256;                                              \
            int r = id >> 3, c = id & 7;                                       \
            uint32_t d = smem_u32(As_ + r*128 + ((c ^ (r & 7)) * 16));         \
            cp_async16(d, aG + (size_t)r*(KSPL*2) + (kt)*128 + c*16);          \
        }                                                                      \
        _Pragma("unroll")                                                      \
        for (int q = 0; q < 2; ++q) {                                          \
            int id = tid + q*256;                                              \
            int r = id >> 3, c = id & 7;                                       \
            uint32_t d = smem_u32(Bs_ + r*128 + ((c ^ (r & 7)) * 16));         \
            cp_async16(d, bG + (size_t)r*(KSPL*2) + (kt)*128 + c*16);          \
        }                                                                      \
        asm volatile("cp.async.commit_group;" ::: "memory");                   \
    } while (0)

    ISSUE_STAGE(0, 0);

    for (int kt = 0; kt < KT_TOTAL; ++kt) {
        int st = kt & 1;
        if (kt + 1 < KT_TOTAL) {
            ISSUE_STAGE(kt + 1, st ^ 1);
            asm volatile("cp.async.wait_group 1;" ::: "memory");
        } else {
            asm volatile("cp.async.wait_group 0;" ::: "memory");
        }
        __syncthreads();

        char* As = smem + st*STAGE_BYTES;
        char* Bs = As + 16384;
        #pragma unroll
        for (int kk = 0; kk < 4; ++kk) {
            uint32_t a[2][4];
            #pragma unroll
            for (int mi = 0; mi < 2; ++mi) {
                int r = wm*32 + mi*16 + (lane & 15);
                int c = kk*2 + (lane >> 4);
                ldmatrix_x4(a[mi], smem_u32(As + r*128 + ((c ^ (r & 7)) * 16)));
            }
            uint32_t b[2][4];
            #pragma unroll
            for (int nj = 0; nj < 2; ++nj) {
                int grp = lane >> 3;
                int r = wn*32 + nj*16 + (grp >> 1)*8 + (lane & 7);
                int c = kk*2 + (grp & 1);
                ldmatrix_x4(b[nj], smem_u32(Bs + r*128 + ((c ^ (r & 7)) * 16)));
            }
            #pragma unroll
            for (int mi = 0; mi < 2; ++mi)
                #pragma unroll
                for (int ni = 0; ni < 4; ++ni)
                    mma16816(acc[mi][ni], a[mi], &b[ni >> 1][(ni & 1) * 2]);
        }
        __syncthreads();
    }

    // ---- fused stage2 epilogue ----
    float* sWq = (float*)smem;
    float* sBias = sWq + 14*64;
    for (int i = tid; i < 14*64; i += 256) {
        int q = i >> 6, c = i & 63;
        sWq[i] = (q < 10) ? wcls[(size_t)(bn + c)*10 + q]
                          : wwh[(size_t)(bn + c)*4 + (q - 10)];
    }
    if (tid < 64) sBias[tid] = bias[bn + tid];
    __syncthreads();

    #pragma unroll
    for (int mi = 0; mi < 2; ++mi) {
        float psA[14], psB[14];
        #pragma unroll
        for (int q = 0; q < 14; ++q) { psA[q] = 0.0f; psB[q] = 0.0f; }
        #pragma unroll
        for (int ni = 0; ni < 4; ++ni) {
            int cl = wn*32 + ni*8 + (lane & 3)*2;
            float b0 = sBias[cl], b1 = sBias[cl+1];
            float hA0 = fmaxf(acc[mi][ni][0] + b0, 0.0f);
            float hA1 = fmaxf(acc[mi][ni][1] + b1, 0.0f);
            float hB0 = fmaxf(acc[mi][ni][2] + b0, 0.0f);
            float hB1 = fmaxf(acc[mi][ni][3] + b1, 0.0f);
            #pragma unroll
            for (int q = 0; q < 14; ++q) {
                float2 ww = *(const float2*)&sWq[q*64 + cl];
                psA[q] += hA0*ww.x + hA1*ww.y;
                psB[q] += hB0*ww.x + hB1*ww.y;
            }
        }
        #pragma unroll
        for (int o = 1; o < 4; o <<= 1) {
            #pragma unroll
            for (int q = 0; q < 14; ++q) {
                psA[q] += __shfl_xor_sync(0xffffffffu, psA[q], o);
                psB[q] += __shfl_xor_sync(0xffffffffu, psB[q], o);
            }
        }
        if ((lane & 3) == 0) {
            int rA = bm + wm*32 + mi*16 + (lane >> 2);
            int rB = rA + 8;
            if (rA < NDET) {
                #pragma unroll
                for (int q = 0; q < 14; ++q) {
                    float* dst = (q < 10) ? &out[OFF_S2CLS + (size_t)rA*10 + q]
                                          : &out[OFF_S2WH  + (size_t)rA*4  + (q-10)];
                    atomicAdd(dst, psA[q]);
                }
            }
            if (rB < NDET) {
                #pragma unroll
                for (int q = 0; q < 14; ++q) {
                    float* dst = (q < 10) ? &out[OFF_S2CLS + (size_t)rB*10 + q]
                                          : &out[OFF_S2WH  + (size_t)rB*4  + (q-10)];
                    atomicAdd(dst, psB[q]);
                }
            }
        }
    }
}

// ---------------- launch ----------------
extern "C" void kernel_launch(void* const* d_in, const int* in_sizes, int n_in,
                              void* d_out, int out_size) {
    const float* feat  = (const float*)d_in[0];
    const float* hm    = (const float*)d_in[1];
    const float* wh    = (const float*)d_in[2];
    const float* offs  = (const float*)d_in[3];
    const float* wfc1  = (const float*)d_in[4];
    const float* bfc1  = (const float*)d_in[5];
    const float* wcls  = (const float*)d_in[6];
    const float* bcls  = (const float*)d_in[7];
    const float* wwh   = (const float*)d_in[8];
    const float* bwh   = (const float*)d_in[9];
    float* out = (float*)d_out;

    k_front<<<NB_FRONT, 256>>>(hm, feat, wh, offs, wfc1, bcls, bwh, out);
    k_gemm_mma<<<dim3(MPAD/BM, HID/BN), 256>>>(bfc1, wcls, wwh, out);
}